// round 11
// baseline (speedup 1.0000x reference)
#include <cuda_runtime.h>

#define N_NODES 100000
#define N_EDGES 1600000
#define D 128
#define BN_EPS 1e-5f
#define LEAKY 0.01f

// ---------------- device scratch (no allocation allowed) ----------------
__device__ int   g_outdeg[N_NODES];
__device__ int   g_indeg [N_NODES];
__device__ int   g_off   [N_NODES];
__device__ int   g_cur   [N_NODES];
__device__ int   g_col   [N_EDGES];
__device__ float g_nsrc  [N_NODES];
__device__ float g_ndst  [N_NODES];
__device__ float g_m     [N_NODES * D];   // aggregation output
__device__ float g_h     [N_NODES * D];   // layer-0 activation

// ---------------- prep kernels ----------------
__global__ void zero_deg_kernel() {
    int i = blockIdx.x * blockDim.x + threadIdx.x;
    if (i < N_NODES) { g_outdeg[i] = 0; g_indeg[i] = 0; }
}

__global__ void degree_kernel(const int* __restrict__ src, const int* __restrict__ dst) {
    int e = blockIdx.x * blockDim.x + threadIdx.x;
    if (e < N_EDGES) {
        atomicAdd(&g_outdeg[src[e]], 1);
        atomicAdd(&g_indeg [dst[e]], 1);
    }
}

__global__ void norm_kernel() {
    int i = blockIdx.x * blockDim.x + threadIdx.x;
    if (i < N_NODES) {
        // +1 for the self loop; degrees are then always >= 1 (max(.,1) is implicit)
        g_nsrc[i] = rsqrtf((float)(g_outdeg[i] + 1));
        g_ndst[i] = rsqrtf((float)(g_indeg [i] + 1));
    }
}

#define SCAN_T 1024
#define CHUNK ((N_NODES + SCAN_T - 1) / SCAN_T)
__global__ void scan_kernel() {
    __shared__ int ps[SCAN_T];
    int t = threadIdx.x;
    int base = t * CHUNK;
    int sum = 0;
    for (int i = 0; i < CHUNK; i++) {
        int idx = base + i;
        if (idx < N_NODES) sum += g_indeg[idx];
    }
    ps[t] = sum;
    __syncthreads();
    // Hillis-Steele inclusive scan over 1024 partials
    for (int off = 1; off < SCAN_T; off <<= 1) {
        int v = (t >= off) ? ps[t - off] : 0;
        __syncthreads();
        ps[t] += v;
        __syncthreads();
    }
    int run = (t == 0) ? 0 : ps[t - 1];
    for (int i = 0; i < CHUNK; i++) {
        int idx = base + i;
        if (idx < N_NODES) {
            g_off[idx] = run;
            g_cur[idx] = run;
            run += g_indeg[idx];
        }
    }
}

__global__ void scatter_kernel(const int* __restrict__ src, const int* __restrict__ dst) {
    int e = blockIdx.x * blockDim.x + threadIdx.x;
    if (e < N_EDGES) {
        int p = atomicAdd(&g_cur[dst[e]], 1);
        g_col[p] = src[e];
    }
}

// ---------------- aggregation: m[i] = ndst[i] * ( nsrc[i]*h[i] + sum_{s in N(i)} nsrc[s]*h[s] )
__global__ void __launch_bounds__(128) agg_kernel(const float* __restrict__ hin,
                                                  float* __restrict__ hout) {
    int node = blockIdx.x;
    int c    = threadIdx.x;
    float acc = hin[node * D + c] * g_nsrc[node];   // self loop
    int beg = g_off[node];
    int cnt = g_indeg[node];
    int k = 0;
    for (; k + 4 <= cnt; k += 4) {
        int s0 = __ldg(&g_col[beg + k + 0]);
        int s1 = __ldg(&g_col[beg + k + 1]);
        int s2 = __ldg(&g_col[beg + k + 2]);
        int s3 = __ldg(&g_col[beg + k + 3]);
        float n0 = __ldg(&g_nsrc[s0]);
        float n1 = __ldg(&g_nsrc[s1]);
        float n2 = __ldg(&g_nsrc[s2]);
        float n3 = __ldg(&g_nsrc[s3]);
        float v0 = __ldg(&hin[s0 * D + c]);
        float v1 = __ldg(&hin[s1 * D + c]);
        float v2 = __ldg(&hin[s2 * D + c]);
        float v3 = __ldg(&hin[s3 * D + c]);
        acc += n0 * v0;
        acc += n1 * v1;
        acc += n2 * v2;
        acc += n3 * v3;
    }
    for (; k < cnt; k++) {
        int s = __ldg(&g_col[beg + k]);
        acc += __ldg(&g_nsrc[s]) * __ldg(&hin[s * D + c]);
    }
    hout[node * D + c] = acc * g_ndst[node];
}

// ---------------- GEMM (+optional BN/leaky): out = M @ W + b ----------------
// block = 128 threads = 4 warps; warp w handles rows [w*8, w*8+8) of a 32-row tile;
// lane l handles cols 4l..4l+3 (float4 W loads, broadcast LDS of m).
#define RTILE 32
#define RW 8
#define GEMM_GRID 296   // 2 blocks per SM (80 KB smem each)

template <bool FUSE_BN>
__global__ void __launch_bounds__(128) gemm_kernel(
    const float* __restrict__ M, const float* __restrict__ W,
    const float* __restrict__ bias,
    const float* __restrict__ gamma, const float* __restrict__ beta,
    const float* __restrict__ mean,  const float* __restrict__ var,
    float* __restrict__ out) {
    extern __shared__ float smem[];
    float* Ws = smem;           // 128*128 floats = 64 KB
    float* ms = smem + D * D;   // RTILE*128 floats = 16 KB

    int tid  = threadIdx.x;
    int warp = tid >> 5;
    int lane = tid & 31;

    for (int i = tid; i < D * D; i += 128) Ws[i] = W[i];

    float4 bi = ((const float4*)bias)[lane];
    float4 sc = make_float4(0.f, 0.f, 0.f, 0.f);
    float4 sh = make_float4(0.f, 0.f, 0.f, 0.f);
    if (FUSE_BN) {
        float4 g  = ((const float4*)gamma)[lane];
        float4 be = ((const float4*)beta )[lane];
        float4 mu = ((const float4*)mean )[lane];
        float4 va = ((const float4*)var  )[lane];
        sc.x = g.x * rsqrtf(va.x + BN_EPS); sh.x = be.x - mu.x * sc.x;
        sc.y = g.y * rsqrtf(va.y + BN_EPS); sh.y = be.y - mu.y * sc.y;
        sc.z = g.z * rsqrtf(va.z + BN_EPS); sh.z = be.z - mu.z * sc.z;
        sc.w = g.w * rsqrtf(va.w + BN_EPS); sh.w = be.w - mu.w * sc.w;
    }
    __syncthreads();

    for (int row0 = blockIdx.x * RTILE; row0 < N_NODES; row0 += gridDim.x * RTILE) {
        int nr = min(RTILE, N_NODES - row0);
        for (int i = tid; i < nr * D; i += 128) ms[i] = M[row0 * D + i];
        __syncthreads();

        float4 acc[RW];
#pragma unroll
        for (int r = 0; r < RW; r++) acc[r] = bi;

#pragma unroll 4
        for (int kk = 0; kk < D; kk++) {
            float4 w = *(const float4*)&Ws[kk * D + 4 * lane];
#pragma unroll
            for (int r = 0; r < RW; r++) {
                float mv = ms[(warp * RW + r) * D + kk];
                acc[r].x += mv * w.x;
                acc[r].y += mv * w.y;
                acc[r].z += mv * w.z;
                acc[r].w += mv * w.w;
            }
        }

#pragma unroll
        for (int r = 0; r < RW; r++) {
            int row = row0 + warp * RW + r;
            if (row < N_NODES) {
                float4 v = acc[r];
                if (FUSE_BN) {
                    v.x = v.x * sc.x + sh.x; v.x = v.x > 0.f ? v.x : LEAKY * v.x;
                    v.y = v.y * sc.y + sh.y; v.y = v.y > 0.f ? v.y : LEAKY * v.y;
                    v.z = v.z * sc.z + sh.z; v.z = v.z > 0.f ? v.z : LEAKY * v.z;
                    v.w = v.w * sc.w + sh.w; v.w = v.w > 0.f ? v.w : LEAKY * v.w;
                }
                *(float4*)&out[row * D + 4 * lane] = v;
            }
        }
        __syncthreads();
    }
}

// ---------------- launch ----------------
extern "C" void kernel_launch(void* const* d_in, const int* in_sizes, int n_in,
                              void* d_out, int out_size) {
    const float* x     = (const float*)d_in[0];
    const int*   src   = (const int*)  d_in[1];
    const int*   dst   = (const int*)  d_in[2];
    const float* W1    = (const float*)d_in[3];
    const float* b1    = (const float*)d_in[4];
    const float* W2    = (const float*)d_in[5];
    const float* b2    = (const float*)d_in[6];
    const float* gamma = (const float*)d_in[7];
    const float* beta  = (const float*)d_in[8];
    const float* rmean = (const float*)d_in[9];
    const float* rvar  = (const float*)d_in[10];
    float* out = (float*)d_out;

    const int gemm_smem = (D * D + RTILE * D) * (int)sizeof(float);  // 80 KB
    cudaFuncSetAttribute(gemm_kernel<true>,
                         cudaFuncAttributeMaxDynamicSharedMemorySize, gemm_smem);
    cudaFuncSetAttribute(gemm_kernel<false>,
                         cudaFuncAttributeMaxDynamicSharedMemorySize, gemm_smem);

    float* d_m = nullptr;
    float* d_h = nullptr;
    cudaGetSymbolAddress((void**)&d_m, g_m);
    cudaGetSymbolAddress((void**)&d_h, g_h);

    const int nodeGrid = (N_NODES + 255) / 256;
    const int edgeGrid = (N_EDGES + 255) / 256;

    // graph prep (rebuilt every replay; degrees/cursors reset each time)
    zero_deg_kernel<<<nodeGrid, 256>>>();
    degree_kernel<<<edgeGrid, 256>>>(src, dst);
    norm_kernel<<<nodeGrid, 256>>>();
    scan_kernel<<<1, SCAN_T>>>();
    scatter_kernel<<<edgeGrid, 256>>>(src, dst);

    // layer 0: conv -> BN(eval) -> leaky
    agg_kernel<<<N_NODES, 128>>>(x, d_m);
    gemm_kernel<true><<<GEMM_GRID, 128, gemm_smem>>>(d_m, W1, b1, gamma, beta,
                                                     rmean, rvar, d_h);

    // layer 1: conv only
    agg_kernel<<<N_NODES, 128>>>(d_h, d_m);
    gemm_kernel<false><<<GEMM_GRID, 128, gemm_smem>>>(d_m, W2, b2, nullptr, nullptr,
                                                      nullptr, nullptr, out);
}

// round 12
// speedup vs baseline: 1.2546x; 1.2546x over previous
#include <cuda_runtime.h>

#define N_NODES 100000
#define N_EDGES 1600000
#define D 128
#define BN_EPS 1e-5f
#define LEAKY 0.01f

// ---------------- device scratch (no allocation allowed) ----------------
__device__ int   g_outdeg[N_NODES];
__device__ int   g_indeg [N_NODES];
__device__ int   g_off   [N_NODES];
__device__ int   g_cur   [N_NODES];
__device__ int   g_col   [N_EDGES];
__device__ float g_nsrc  [N_NODES];
__device__ float g_ndst  [N_NODES];
__device__ float g_m     [N_NODES * D];   // aggregation output
__device__ float g_h     [N_NODES * D];   // layer-0 activation

#define SB 512
#define NSB ((N_NODES + SB - 1) / SB)     // 196 scan blocks
__device__ int g_blocksum[NSB];
__device__ int g_blockoff[256];

// ---------------- prep kernels ----------------
__global__ void zero_deg_kernel() {
    int i = blockIdx.x * blockDim.x + threadIdx.x;
    if (i < N_NODES) { g_outdeg[i] = 0; g_indeg[i] = 0; }
}

__global__ void degree_kernel(const int* __restrict__ src, const int* __restrict__ dst) {
    int e = blockIdx.x * blockDim.x + threadIdx.x;
    if (e < N_EDGES) {
        atomicAdd(&g_outdeg[src[e]], 1);
        atomicAdd(&g_indeg [dst[e]], 1);
    }
}

__global__ void norm_kernel() {
    int i = blockIdx.x * blockDim.x + threadIdx.x;
    if (i < N_NODES) {
        // +1 for the self loop; degrees are then always >= 1
        g_nsrc[i] = rsqrtf((float)(g_outdeg[i] + 1));
        g_ndst[i] = rsqrtf((float)(g_indeg [i] + 1));
    }
}

// ---------------- two-level scan of g_indeg -> g_off / g_cur ----------------
__global__ void __launch_bounds__(SB) blocksum_kernel() {
    __shared__ int sh[SB];
    int t = threadIdx.x;
    int i = blockIdx.x * SB + t;
    sh[t] = (i < N_NODES) ? g_indeg[i] : 0;
    __syncthreads();
#pragma unroll
    for (int off = SB / 2; off > 0; off >>= 1) {
        if (t < off) sh[t] += sh[t + off];
        __syncthreads();
    }
    if (t == 0) g_blocksum[blockIdx.x] = sh[0];
}

__global__ void __launch_bounds__(256) blockscan_kernel() {
    __shared__ int sh[256];
    int t = threadIdx.x;
    int v = (t < NSB) ? g_blocksum[t] : 0;
    sh[t] = v;
    __syncthreads();
#pragma unroll
    for (int off = 1; off < 256; off <<= 1) {
        int u = (t >= off) ? sh[t - off] : 0;
        __syncthreads();
        sh[t] += u;
        __syncthreads();
    }
    g_blockoff[t] = sh[t] - v;   // exclusive prefix of block sums
}

__global__ void __launch_bounds__(SB) offsets_kernel() {
    __shared__ int sh[SB];
    int t = threadIdx.x;
    int i = blockIdx.x * SB + t;
    int v = (i < N_NODES) ? g_indeg[i] : 0;
    sh[t] = v;
    __syncthreads();
#pragma unroll
    for (int off = 1; off < SB; off <<= 1) {
        int u = (t >= off) ? sh[t - off] : 0;
        __syncthreads();
        sh[t] += u;
        __syncthreads();
    }
    if (i < N_NODES) {
        int o = g_blockoff[blockIdx.x] + sh[t] - v;   // global exclusive prefix
        g_off[i] = o;
        g_cur[i] = o;
    }
}

__global__ void scatter_kernel(const int* __restrict__ src, const int* __restrict__ dst) {
    int e = blockIdx.x * blockDim.x + threadIdx.x;
    if (e < N_EDGES) {
        int p = atomicAdd(&g_cur[dst[e]], 1);
        g_col[p] = src[e];
    }
}

// ---------------- aggregation: m[i] = ndst[i] * ( nsrc[i]*h[i] + sum_{s in N(i)} nsrc[s]*h[s] )
__global__ void __launch_bounds__(128) agg_kernel(const float* __restrict__ hin,
                                                  float* __restrict__ hout) {
    int node = blockIdx.x;
    int c    = threadIdx.x;
    float acc = hin[node * D + c] * g_nsrc[node];   // self loop
    int beg = g_off[node];
    int cnt = g_indeg[node];
    int k = 0;
    for (; k + 4 <= cnt; k += 4) {
        int s0 = __ldg(&g_col[beg + k + 0]);
        int s1 = __ldg(&g_col[beg + k + 1]);
        int s2 = __ldg(&g_col[beg + k + 2]);
        int s3 = __ldg(&g_col[beg + k + 3]);
        float n0 = __ldg(&g_nsrc[s0]);
        float n1 = __ldg(&g_nsrc[s1]);
        float n2 = __ldg(&g_nsrc[s2]);
        float n3 = __ldg(&g_nsrc[s3]);
        float v0 = __ldg(&hin[s0 * D + c]);
        float v1 = __ldg(&hin[s1 * D + c]);
        float v2 = __ldg(&hin[s2 * D + c]);
        float v3 = __ldg(&hin[s3 * D + c]);
        acc += n0 * v0;
        acc += n1 * v1;
        acc += n2 * v2;
        acc += n3 * v3;
    }
    for (; k < cnt; k++) {
        int s = __ldg(&g_col[beg + k]);
        acc += __ldg(&g_nsrc[s]) * __ldg(&hin[s * D + c]);
    }
    hout[node * D + c] = acc * g_ndst[node];
}

// ---------------- GEMM (+optional BN/leaky): out = M @ W + b ----------------
#define RTILE 32
#define RW 8
#define GEMM_GRID 296   // 2 blocks per SM (80 KB smem each)

template <bool FUSE_BN>
__global__ void __launch_bounds__(128) gemm_kernel(
    const float* __restrict__ M, const float* __restrict__ W,
    const float* __restrict__ bias,
    const float* __restrict__ gamma, const float* __restrict__ beta,
    const float* __restrict__ mean,  const float* __restrict__ var,
    float* __restrict__ out) {
    extern __shared__ float smem[];
    float* Ws = smem;           // 128*128 floats = 64 KB
    float* ms = smem + D * D;   // RTILE*128 floats = 16 KB

    int tid  = threadIdx.x;
    int warp = tid >> 5;
    int lane = tid & 31;

    for (int i = tid; i < D * D; i += 128) Ws[i] = W[i];

    float4 bi = ((const float4*)bias)[lane];
    float4 sc = make_float4(0.f, 0.f, 0.f, 0.f);
    float4 sh = make_float4(0.f, 0.f, 0.f, 0.f);
    if (FUSE_BN) {
        float4 g  = ((const float4*)gamma)[lane];
        float4 be = ((const float4*)beta )[lane];
        float4 mu = ((const float4*)mean )[lane];
        float4 va = ((const float4*)var  )[lane];
        sc.x = g.x * rsqrtf(va.x + BN_EPS); sh.x = be.x - mu.x * sc.x;
        sc.y = g.y * rsqrtf(va.y + BN_EPS); sh.y = be.y - mu.y * sc.y;
        sc.z = g.z * rsqrtf(va.z + BN_EPS); sh.z = be.z - mu.z * sc.z;
        sc.w = g.w * rsqrtf(va.w + BN_EPS); sh.w = be.w - mu.w * sc.w;
    }
    __syncthreads();

    for (int row0 = blockIdx.x * RTILE; row0 < N_NODES; row0 += gridDim.x * RTILE) {
        int nr = min(RTILE, N_NODES - row0);
        for (int i = tid; i < nr * D; i += 128) ms[i] = M[row0 * D + i];
        __syncthreads();

        float4 acc[RW];
#pragma unroll
        for (int r = 0; r < RW; r++) acc[r] = bi;

#pragma unroll 4
        for (int kk = 0; kk < D; kk++) {
            float4 w = *(const float4*)&Ws[kk * D + 4 * lane];
#pragma unroll
            for (int r = 0; r < RW; r++) {
                float mv = ms[(warp * RW + r) * D + kk];
                acc[r].x += mv * w.x;
                acc[r].y += mv * w.y;
                acc[r].z += mv * w.z;
                acc[r].w += mv * w.w;
            }
        }

#pragma unroll
        for (int r = 0; r < RW; r++) {
            int row = row0 + warp * RW + r;
            if (row < N_NODES) {
                float4 v = acc[r];
                if (FUSE_BN) {
                    v.x = v.x * sc.x + sh.x; v.x = v.x > 0.f ? v.x : LEAKY * v.x;
                    v.y = v.y * sc.y + sh.y; v.y = v.y > 0.f ? v.y : LEAKY * v.y;
                    v.z = v.z * sc.z + sh.z; v.z = v.z > 0.f ? v.z : LEAKY * v.z;
                    v.w = v.w * sc.w + sh.w; v.w = v.w > 0.f ? v.w : LEAKY * v.w;
                }
                *(float4*)&out[row * D + 4 * lane] = v;
            }
        }
        __syncthreads();
    }
}

// ---------------- launch ----------------
extern "C" void kernel_launch(void* const* d_in, const int* in_sizes, int n_in,
                              void* d_out, int out_size) {
    const float* x     = (const float*)d_in[0];
    const int*   src   = (const int*)  d_in[1];
    const int*   dst   = (const int*)  d_in[2];
    const float* W1    = (const float*)d_in[3];
    const float* b1    = (const float*)d_in[4];
    const float* W2    = (const float*)d_in[5];
    const float* b2    = (const float*)d_in[6];
    const float* gamma = (const float*)d_in[7];
    const float* beta  = (const float*)d_in[8];
    const float* rmean = (const float*)d_in[9];
    const float* rvar  = (const float*)d_in[10];
    float* out = (float*)d_out;

    const int gemm_smem = (D * D + RTILE * D) * (int)sizeof(float);  // 80 KB
    cudaFuncSetAttribute(gemm_kernel<true>,
                         cudaFuncAttributeMaxDynamicSharedMemorySize, gemm_smem);
    cudaFuncSetAttribute(gemm_kernel<false>,
                         cudaFuncAttributeMaxDynamicSharedMemorySize, gemm_smem);

    float* d_m = nullptr;
    float* d_h = nullptr;
    cudaGetSymbolAddress((void**)&d_m, g_m);
    cudaGetSymbolAddress((void**)&d_h, g_h);

    const int nodeGrid = (N_NODES + 255) / 256;
    const int edgeGrid = (N_EDGES + 255) / 256;

    // graph prep (rebuilt every replay; degrees/cursors reset each time)
    zero_deg_kernel<<<nodeGrid, 256>>>();
    degree_kernel<<<edgeGrid, 256>>>(src, dst);
    norm_kernel<<<nodeGrid, 256>>>();
    blocksum_kernel<<<NSB, SB>>>();
    blockscan_kernel<<<1, 256>>>();
    offsets_kernel<<<NSB, SB>>>();
    scatter_kernel<<<edgeGrid, 256>>>(src, dst);

    // layer 0: conv -> BN(eval) -> leaky
    agg_kernel<<<N_NODES, 128>>>(x, d_m);
    gemm_kernel<true><<<GEMM_GRID, 128, gemm_smem>>>(d_m, W1, b1, gamma, beta,
                                                     rmean, rvar, d_h);

    // layer 1: conv only
    agg_kernel<<<N_NODES, 128>>>(d_h, d_m);
    gemm_kernel<false><<<GEMM_GRID, 128, gemm_smem>>>(d_m, W2, b2, nullptr, nullptr,
                                                      nullptr, nullptr, out);
}